// round 1
// baseline (speedup 1.0000x reference)
#include <cuda_runtime.h>

// Problem constants
#define CC   256
#define HH   128
#define WW   128
#define BB   8
#define KK   9
#define PP   4

// Tiling
#define KC      16              // input channels per chunk
#define NCHUNK  (CC / KC)       // 16
#define JC      (4 * KC)        // 64 y-channels per chunk
#define WSTRIDE 260             // padded [k][o] stride (floats), 16B aligned

// Shared memory layout (in floats)
#define XSTRIDE_C (9 * WW)                  // 1152
#define XOFF 0
#define XSZ  (KC * XSTRIDE_C)               // 18432
#define WOFF (XOFF + XSZ)                   // 18432
#define WSZ  (JC * WSTRIDE)                 // 16640
#define YOFF (WOFF + WSZ)                   // 35072
#define YSZ  (JC * WW)                      // 8192
#define DWOFF (YOFF + YSZ)                  // 43264
#define DWSZ  (4 * CC * KK)                 // 9216
#define SMEM_FLOATS (DWOFF + DWSZ)          // 52480
#define SMEM_BYTES  (SMEM_FLOATS * 4)       // 209920

__global__ __launch_bounds__(256, 1)
void spatial_encoder_fused(const float* __restrict__ x,
                           const float* __restrict__ wh1,
                           const float* __restrict__ wh2,
                           const float* __restrict__ wv1,
                           const float* __restrict__ wv2,
                           const float* __restrict__ wproj,
                           float* __restrict__ out)
{
    extern __shared__ float sm[];
    float* xs  = sm + XOFF;   // [KC][9][128]
    float* wc  = sm + WOFF;   // [JC][WSTRIDE] (k-major, o contiguous)
    float* ys  = sm + YOFF;   // [JC][128]
    float* wsm = sm + DWOFF;  // [4][256][9] depthwise weights

    const int h = blockIdx.x;   // row
    const int b = blockIdx.y;   // batch
    const int t = threadIdx.x;

    // GEMM thread tiling: 16x16 thread grid, each thread 16 o x 8 w
    const int tid_o  = t >> 4;
    const int tid_w  = t & 15;
    const int o_base = tid_o * 16;
    const int w_base = tid_w * 8;

    // Depthwise thread mapping: 128 w-columns x 2 j-groups
    const int dw_w  = t & 127;
    const int dw_tg = t >> 7;   // 0 or 1

    // ---- one-time: stage all depthwise weights into smem ----
    for (int idx = t; idx < DWSZ; idx += 256) {
        const int sel = idx / (CC * KK);
        const int off = idx - sel * (CC * KK);
        const float* p = (sel == 0) ? wh1 : (sel == 1) ? wh2 : (sel == 2) ? wv1 : wv2;
        wsm[idx] = p[off];
    }

    float acc[16][8];
    #pragma unroll
    for (int i = 0; i < 16; ++i)
        #pragma unroll
        for (int j = 0; j < 8; ++j)
            acc[i][j] = 0.f;

    const float* xb = x + ((long)b * CC) * (HH * WW);

    for (int chunk = 0; chunk < NCHUNK; ++chunk) {
        const int c0 = chunk * KC;

        __syncthreads();   // previous GEMM finished reading wc/ys; xs free

        // ---- phase 1a: load x chunk (with vertical halo, zero-padded) ----
        for (int idx = t; idx < XSZ; idx += 256) {
            const int ci  = idx / XSTRIDE_C;
            const int rem = idx - ci * XSTRIDE_C;
            const int r   = rem >> 7;          // 0..8
            const int ww  = rem & 127;
            const int hh  = h + r - PP;
            float v = 0.f;
            if ((unsigned)hh < (unsigned)HH)
                v = xb[((long)(c0 + ci) * HH + hh) * WW + ww];
            xs[idx] = v;
        }

        // ---- phase 1b: load wproj slice, transposed to [j][o] ----
        // j = br*16 + ci  <->  global cc = br*256 + c0 + ci
        for (int idx = t; idx < JC * CC; idx += 256) {
            const int o  = idx >> 6;      // 0..255
            const int j  = idx & 63;
            const int br = j >> 4;
            const int ci = j & 15;
            wc[j * WSTRIDE + o] = wproj[o * (4 * CC) + br * CC + c0 + ci];
        }

        __syncthreads();

        // ---- phase 2: depthwise -> ys[j][w] ----
        {
            const int jend = dw_tg * 32 + 32;
            for (int j = dw_tg * 32; j < jend; ++j) {
                const int br = j >> 4;
                const int cl = j & 15;
                const float* wp = wsm + br * (CC * KK) + (c0 + cl) * KK;
                float s = 0.f;
                if (br < 2) {
                    const float* xr = xs + cl * XSTRIDE_C + PP * WW;
                    #pragma unroll
                    for (int k = 0; k < KK; ++k) {
                        const int wx = dw_w + k - PP;
                        if ((unsigned)wx < (unsigned)WW)
                            s = fmaf(wp[k], xr[wx], s);
                    }
                } else {
                    const float* xc = xs + cl * XSTRIDE_C + dw_w;
                    #pragma unroll
                    for (int k = 0; k < KK; ++k)
                        s = fmaf(wp[k], xc[k * WW], s);
                }
                ys[j * WW + dw_w] = s;
            }
        }

        __syncthreads();

        // ---- phase 3: rank-JC GEMM update ----
        #pragma unroll 1
        for (int k = 0; k < JC; ++k) {
            const float4 ya = *(const float4*)(ys + k * WW + w_base);
            const float4 yb4 = *(const float4*)(ys + k * WW + w_base + 4);
            float yv[8] = {ya.x, ya.y, ya.z, ya.w, yb4.x, yb4.y, yb4.z, yb4.w};
            const float* wrow = wc + k * WSTRIDE + o_base;
            #pragma unroll
            for (int g = 0; g < 4; ++g) {
                const float4 wv4 = *(const float4*)(wrow + g * 4);
                const float wv[4] = {wv4.x, wv4.y, wv4.z, wv4.w};
                #pragma unroll
                for (int ii = 0; ii < 4; ++ii)
                    #pragma unroll
                    for (int jj = 0; jj < 8; ++jj)
                        acc[g * 4 + ii][jj] = fmaf(wv[ii], yv[jj], acc[g * 4 + ii][jj]);
            }
        }
    }

    // ---- epilogue: ReLU + store ----
    float* op = out + (((long)b * CC + o_base) * HH + h) * WW + w_base;
    #pragma unroll
    for (int i = 0; i < 16; ++i) {
        float4 r0, r1;
        r0.x = fmaxf(acc[i][0], 0.f);
        r0.y = fmaxf(acc[i][1], 0.f);
        r0.z = fmaxf(acc[i][2], 0.f);
        r0.w = fmaxf(acc[i][3], 0.f);
        r1.x = fmaxf(acc[i][4], 0.f);
        r1.y = fmaxf(acc[i][5], 0.f);
        r1.z = fmaxf(acc[i][6], 0.f);
        r1.w = fmaxf(acc[i][7], 0.f);
        *(float4*)(op + (long)i * (HH * WW))     = r0;
        *(float4*)(op + (long)i * (HH * WW) + 4) = r1;
    }
}

extern "C" void kernel_launch(void* const* d_in, const int* in_sizes, int n_in,
                              void* d_out, int out_size)
{
    const float* x     = (const float*)d_in[0];
    const float* wh1   = (const float*)d_in[1];
    const float* wh2   = (const float*)d_in[2];
    const float* wv1   = (const float*)d_in[3];
    const float* wv2   = (const float*)d_in[4];
    const float* wproj = (const float*)d_in[5];
    float* out = (float*)d_out;

    cudaFuncSetAttribute(spatial_encoder_fused,
                         cudaFuncAttributeMaxDynamicSharedMemorySize, SMEM_BYTES);

    dim3 grid(HH, BB);
    spatial_encoder_fused<<<grid, 256, SMEM_BYTES>>>(x, wh1, wh2, wv1, wv2, wproj, out);
}

// round 3
// speedup vs baseline: 3.4353x; 3.4353x over previous
#include <cuda_runtime.h>
#include <cuda_bf16.h>
#include <cstdint>

#define HH 128
#define WW 128
#define BB 8
#define NCH 32           // k-chunks (8 input channels -> 32 y-channels each)

// ---- smem byte layout ----
#define XB_OFF 0                      // 2 x 36864 : x fp32 [8ch][9rows][128]
#define XB_SZ  36864
#define AB_OFF 73728                  // 2 bufs x 2(hi/lo) x 256 rows x 80B
#define AB_BUF 40960
#define AB_S   20480
#define YB_OFF 155648                 // 2(hi/lo) x 128 rows x 80B
#define YB_S   10240
#define DW_OFF 176128                 // 9216 floats (4 x 256 x 9)
#define SMEM_BYTES 212992

// wproj pre-split: [chunk(32)][s(hi/lo)][m(256)][16 words(=32 bf16 k-vals)]
__device__ uint32_t g_A_prep[32 * 2 * 256 * 16];

// ================= helpers =================
__device__ __forceinline__ uint32_t smem_u32(const void* p) {
    uint32_t a;
    asm("{ .reg .u64 t; cvta.to.shared.u64 t, %1; cvt.u32.u64 %0, t; }" : "=r"(a) : "l"(p));
    return a;
}
__device__ __forceinline__ void cpa16(uint32_t dst, const void* src, int sz) {
    unsigned long long g = (unsigned long long)__cvta_generic_to_global((void*)src);
    asm volatile("cp.async.cg.shared.global [%0], [%1], 16, %2;" :: "r"(dst), "l"(g), "r"(sz));
}
__device__ __forceinline__ void ldsm4(uint32_t* r, uint32_t addr) {
    asm volatile("ldmatrix.sync.aligned.m8n8.x4.shared.b16 {%0,%1,%2,%3}, [%4];"
        : "=r"(r[0]), "=r"(r[1]), "=r"(r[2]), "=r"(r[3]) : "r"(addr));
}
__device__ __forceinline__ void mma_bf16(float* d, const uint32_t* a, const uint32_t* b) {
    asm volatile("mma.sync.aligned.m16n8k16.row.col.f32.bf16.bf16.f32 "
        "{%0,%1,%2,%3}, {%4,%5,%6,%7}, {%8,%9}, {%0,%1,%2,%3};"
        : "+f"(d[0]), "+f"(d[1]), "+f"(d[2]), "+f"(d[3])
        : "r"(a[0]), "r"(a[1]), "r"(a[2]), "r"(a[3]), "r"(b[0]), "r"(b[1]));
}
__device__ __forceinline__ void cvt2(float a, float b, uint32_t& hi, uint32_t& lo) {
    __nv_bfloat16 ah = __float2bfloat16(a), bh = __float2bfloat16(b);
    __nv_bfloat16 al = __float2bfloat16(a - __bfloat162float(ah));
    __nv_bfloat16 bl = __float2bfloat16(b - __bfloat162float(bh));
    hi = (uint32_t)__bfloat16_as_ushort(ah) | ((uint32_t)__bfloat16_as_ushort(bh) << 16);
    lo = (uint32_t)__bfloat16_as_ushort(al) | ((uint32_t)__bfloat16_as_ushort(bl) << 16);
}

// ================= prep: wproj -> bf16 hi/lo slices =================
__global__ void se_prep(const float* __restrict__ wproj)
{
    int widx = blockIdx.x * 256 + threadIdx.x;      // 262144
    int kp = widx & 15;
    int m  = (widx >> 4) & 255;
    int s  = (widx >> 12) & 1;
    int c  = widx >> 13;
    uint32_t outw = 0;
    #pragma unroll
    for (int e = 0; e < 2; ++e) {
        int k  = kp * 2 + e;          // 0..31 within chunk
        int br = k >> 3, lc = k & 7;
        float v = wproj[m * 1024 + br * 256 + c * 8 + lc];
        __nv_bfloat16 hi = __float2bfloat16(v);
        __nv_bfloat16 val = s ? __float2bfloat16(v - __bfloat162float(hi)) : hi;
        outw |= (uint32_t)__bfloat16_as_ushort(val) << (16 * e);
    }
    g_A_prep[((c * 2 + s) * 256 + m) * 16 + kp] = outw;
}

// ================= main =================
__device__ __forceinline__ void prefetch(const float* xb, int c, int dbuf,
                                         uint32_t sb, int h, int t)
{
    for (int i = t; i < 2304; i += 512) {
        int ci = i / 288, rem = i - ci * 288;
        int r = rem >> 5, q = rem & 31;
        int hh = h + r - 4;
        int hc = hh < 0 ? 0 : (hh > 127 ? 127 : hh);
        const float* src = xb + (((long)(c * 8 + ci)) * HH + hc) * WW + q * 4;
        uint32_t dst = sb + XB_OFF + dbuf * XB_SZ + (uint32_t)((ci * 1152 + r * 128 + q * 4) * 4);
        cpa16(dst, src, ((unsigned)hh < 128u) ? 16 : 0);
    }
    for (int i = t; i < 2048; i += 512) {
        int s = i >> 10, rem = i & 1023;
        int m = rem >> 2, q = rem & 3;
        const uint32_t* src = &g_A_prep[((c * 2 + s) * 256 + m) * 16 + q * 4];
        uint32_t dst = sb + AB_OFF + dbuf * AB_BUF + s * AB_S + (uint32_t)(m * 80 + q * 16);
        cpa16(dst, src, 16);
    }
}

__global__ __launch_bounds__(512, 1)
void se_main(const float* __restrict__ x,
             const float* __restrict__ wh1, const float* __restrict__ wh2,
             const float* __restrict__ wv1, const float* __restrict__ wv2,
             float* __restrict__ out)
{
    extern __shared__ char smc[];
    float* smf = (float*)smc;
    const uint32_t sb = smem_u32(smc);
    const int h = blockIdx.x, b = blockIdx.y;
    const int t = threadIdx.x, lane = t & 31, wid = t >> 5;
    const int wm = (wid & 3) * 64, wn = (wid >> 2) * 32;

    float* dws = smf + DW_OFF / 4;
    for (int i = t; i < 9216; i += 512) {
        int sel = i / 2304, off = i - sel * 2304;
        const float* p = (sel == 0) ? wh1 : (sel == 1) ? wh2 : (sel == 2) ? wv1 : wv2;
        dws[i] = p[off];
    }

    const float* xb = x + (long)b * 256 * HH * WW;

    prefetch(xb, 0, 0, sb, h, t);
    asm volatile("cp.async.commit_group;" ::: "memory");

    float acc[4][4][4];
    #pragma unroll
    for (int i = 0; i < 4; ++i)
        #pragma unroll
        for (int j = 0; j < 4; ++j)
            #pragma unroll
            for (int e = 0; e < 4; ++e) acc[i][j][e] = 0.f;

    const int n = t & 127, g = t >> 7;

    for (int c = 0; c < NCH; ++c) {
        const int buf = c & 1;
        asm volatile("cp.async.wait_group 0;" ::: "memory");
        __syncthreads();
        if (c + 1 < NCH) {
            prefetch(xb, c + 1, buf ^ 1, sb, h, t);
            asm volatile("cp.async.commit_group;" ::: "memory");
        }

        {   // depthwise
            const float* xs = smf + (XB_OFF + buf * XB_SZ) / 4;
            const float* wb = dws + g * 2304 + (c * 8) * 9;
            float y[8];
            if (g < 2) {
                #pragma unroll
                for (int lc = 0; lc < 8; ++lc) {
                    const float* xr = xs + lc * 1152 + 4 * 128;
                    const float* w = wb + lc * 9;
                    float s = 0.f;
                    #pragma unroll
                    for (int k = 0; k < 9; ++k) {
                        int nx = n + k - 4;
                        if ((unsigned)nx < 128u) s = fmaf(w[k], xr[nx], s);
                    }
                    y[lc] = s;
                }
            } else {
                #pragma unroll
                for (int lc = 0; lc < 8; ++lc) {
                    const float* xc = xs + lc * 1152 + n;
                    const float* w = wb + lc * 9;
                    float s = 0.f;
                    #pragma unroll
                    for (int k = 0; k < 9; ++k) s = fmaf(w[k], xc[k * 128], s);
                    y[lc] = s;
                }
            }
            uint32_t hv[4], lv[4];
            #pragma unroll
            for (int p = 0; p < 4; ++p) cvt2(y[2 * p], y[2 * p + 1], hv[p], lv[p]);
            *(uint4*)(smc + YB_OFF + n * 80 + g * 16) = make_uint4(hv[0], hv[1], hv[2], hv[3]);
            *(uint4*)(smc + YB_OFF + YB_S + n * 80 + g * 16) = make_uint4(lv[0], lv[1], lv[2], lv[3]);
        }
        __syncthreads();

        {   // mma: 3-pass split bf16, k = 32 (2 k-steps of 16)
            const uint32_t ab = sb + AB_OFF + buf * AB_BUF;
            const uint32_t yb = sb + YB_OFF;
            const uint32_t arow = (uint32_t)(wm + (lane & 15));
            const uint32_t acol8 = (uint32_t)((lane >> 4) << 3);
            const uint32_t brow = (uint32_t)(wn + (lane & 7) + ((lane >> 4) << 3));
            const uint32_t bcol8 = (uint32_t)(lane & 8);
            #pragma unroll
            for (int ks = 0; ks < 2; ++ks) {
                const uint32_t k0 = ks * 16;
                const uint32_t aoff = arow * 80 + (k0 + acol8) * 2;
                const uint32_t boff = brow * 80 + (k0 + bcol8) * 2;
                uint32_t ah[16], bh[8];
                #pragma unroll
                for (int mt = 0; mt < 4; ++mt) ldsm4(&ah[mt * 4], ab + aoff + mt * 16 * 80);
                ldsm4(&bh[0], yb + boff);
                ldsm4(&bh[4], yb + boff + 16 * 80);
                #pragma unroll
                for (int mt = 0; mt < 4; ++mt)
                    #pragma unroll
                    for (int nt = 0; nt < 4; ++nt)
                        mma_bf16(acc[mt][nt], &ah[mt * 4], &bh[nt * 2]);
                uint32_t al[16];
                #pragma unroll
                for (int mt = 0; mt < 4; ++mt) ldsm4(&al[mt * 4], ab + AB_S + aoff + mt * 16 * 80);
                #pragma unroll
                for (int mt = 0; mt < 4; ++mt)
                    #pragma unroll
                    for (int nt = 0; nt < 4; ++nt)
                        mma_bf16(acc[mt][nt], &al[mt * 4], &bh[nt * 2]);
                uint32_t bl[8];
                ldsm4(&bl[0], yb + YB_S + boff);
                ldsm4(&bl[4], yb + YB_S + boff + 16 * 80);
                #pragma unroll
                for (int mt = 0; mt < 4; ++mt)
                    #pragma unroll
                    for (int nt = 0; nt < 4; ++nt)
                        mma_bf16(acc[mt][nt], &ah[mt * 4], &bl[nt * 2]);
            }
        }
    }

    const int g2 = lane >> 2, cq = lane & 3;
    #pragma unroll
    for (int mt = 0; mt < 4; ++mt) {
        const int o0 = wm + mt * 16 + g2;
        #pragma unroll
        for (int nt = 0; nt < 4; ++nt) {
            const int n0 = wn + nt * 8 + cq * 2;
            float* p = out + (((long)(b * 256 + o0)) * HH + h) * WW + n0;
            float2 v0, v1;
            v0.x = fmaxf(acc[mt][nt][0], 0.f);
            v0.y = fmaxf(acc[mt][nt][1], 0.f);
            v1.x = fmaxf(acc[mt][nt][2], 0.f);
            v1.y = fmaxf(acc[mt][nt][3], 0.f);
            *(float2*)p = v0;
            *(float2*)(p + 8L * HH * WW) = v1;
        }
    }
}

// ================= launch =================
extern "C" void kernel_launch(void* const* d_in, const int* in_sizes, int n_in,
                              void* d_out, int out_size)
{
    const float* x     = (const float*)d_in[0];
    const float* wh1   = (const float*)d_in[1];
    const float* wh2   = (const float*)d_in[2];
    const float* wv1   = (const float*)d_in[3];
    const float* wv2   = (const float*)d_in[4];
    const float* wproj = (const float*)d_in[5];
    float* out = (float*)d_out;

    se_prep<<<1024, 256>>>(wproj);

    cudaFuncSetAttribute(se_main, cudaFuncAttributeMaxDynamicSharedMemorySize, SMEM_BYTES);
    dim3 grid(HH, BB);
    se_main<<<grid, 512, SMEM_BYTES>>>(x, wh1, wh2, wv1, wv2, out);
}

// round 4
// speedup vs baseline: 4.2884x; 1.2483x over previous
#include <cuda_runtime.h>
#include <cuda_bf16.h>
#include <cstdint>

#define HH 128
#define WW 128
#define BB 8
#define NCH 32            // 32 k-chunks; each = 8 input channels x 4 branches = 32 y-channels

// ---- smem byte layout ----
#define XB_OFF 0                      // 2 x 36864 : x fp32 [8ch][9rows][128]
#define XB_SZ  36864
#define AB_OFF 73728                  // 2 x 36864 : A tf32 [256 m][36 words] (stride 144B)
#define AB_SZ  36864
#define YB_OFF 147456                 // 2 x 17408 : y tf32 [32 k][136 words] (stride 544B)
#define YB_SZ  17408
#define DW_OFF 182272                 // 9216 floats (4 x 256 x 9)
#define SMEM_BYTES 219136

// wproj pre-converted to tf32: [chunk(32)][m(256)][k(32)] u32
__device__ uint32_t g_A_tf32[32 * 256 * 32];

// ================= helpers =================
__device__ __forceinline__ uint32_t smem_u32(const void* p) {
    uint32_t a;
    asm("{ .reg .u64 t; cvta.to.shared.u64 t, %1; cvt.u32.u64 %0, t; }" : "=r"(a) : "l"(p));
    return a;
}
__device__ __forceinline__ void cpa16(uint32_t dst, const void* src, int sz) {
    unsigned long long g = (unsigned long long)__cvta_generic_to_global((void*)src);
    asm volatile("cp.async.cg.shared.global [%0], [%1], 16, %2;" :: "r"(dst), "l"(g), "r"(sz));
}
__device__ __forceinline__ uint32_t f2tf32(float v) {
    uint32_t u;
    asm("cvt.rna.tf32.f32 %0, %1;" : "=r"(u) : "f"(v));
    return u;
}
__device__ __forceinline__ void mma_tf32(float* d, const uint32_t* a, const uint32_t* b) {
    asm volatile("mma.sync.aligned.m16n8k8.row.col.f32.tf32.tf32.f32 "
        "{%0,%1,%2,%3}, {%4,%5,%6,%7}, {%8,%9}, {%0,%1,%2,%3};"
        : "+f"(d[0]), "+f"(d[1]), "+f"(d[2]), "+f"(d[3])
        : "r"(a[0]), "r"(a[1]), "r"(a[2]), "r"(a[3]), "r"(b[0]), "r"(b[1]));
}

// ================= prep: wproj -> tf32, chunked layout =================
__global__ void se_prep(const float* __restrict__ wproj)
{
    int idx = blockIdx.x * 256 + threadIdx.x;   // 262144
    int k = idx & 31;
    int m = (idx >> 5) & 255;
    int c = idx >> 13;
    int br = k >> 3, lc = k & 7;
    float v = wproj[m * 1024 + br * 256 + c * 8 + lc];
    g_A_tf32[(c * 256 + m) * 32 + k] = f2tf32(v);
}

// ================= main =================
__global__ __launch_bounds__(512, 1)
void se_main(const float* __restrict__ x,
             const float* __restrict__ wh1, const float* __restrict__ wh2,
             const float* __restrict__ wv1, const float* __restrict__ wv2,
             float* __restrict__ out)
{
    extern __shared__ char smc[];
    float* smf = (float*)smc;
    const uint32_t sb = smem_u32(smc);
    const int h = blockIdx.x, b = blockIdx.y;
    const int t = threadIdx.x, lane = t & 31, wid = t >> 5;
    const int wm = (wid & 3) * 64;       // output-channel tile base (M)
    const int wn = (wid >> 2) * 32;      // pixel tile base (N)
    const int n = t & 127, g = t >> 7;   // depthwise: pixel n, branch g

    // stage depthwise weights (fp32)
    float* dws = smf + DW_OFF / 4;
    for (int i = t; i < 9216; i += 512) {
        int sel = i / 2304, off = i - sel * 2304;
        const float* p = (sel == 0) ? wh1 : (sel == 1) ? wh2 : (sel == 2) ? wv1 : wv2;
        dws[i] = p[off];
    }

    const float* xb = x + (long)b * 256 * HH * WW;

    // ---- prefetch lambdas ----
    auto px = [&](int c, int dbuf) {
        for (int i = t; i < 2304; i += 512) {
            int ci = i / 288, rem = i - ci * 288;
            int r = rem >> 5, q = rem & 31;
            int hh = h + r - 4;
            int hcl = hh < 0 ? 0 : (hh > 127 ? 127 : hh);
            const float* src = xb + (((long)(c * 8 + ci)) * HH + hcl) * WW + q * 4;
            uint32_t dst = sb + XB_OFF + dbuf * XB_SZ + (uint32_t)((ci * 1152 + r * 128 + q * 4) * 4);
            cpa16(dst, src, ((unsigned)hh < 128u) ? 16 : 0);
        }
    };
    auto pa = [&](int c, int dbuf) {
        for (int i = t; i < 2048; i += 512) {
            int m = i >> 3, q = i & 7;
            const uint32_t* src = &g_A_tf32[(c * 256 + m) * 32 + q * 4];
            uint32_t dst = sb + AB_OFF + dbuf * AB_SZ + (uint32_t)(m * 144 + q * 16);
            cpa16(dst, src, 16);
        }
    };

    // ---- depthwise: chunk cc from xbuf -> y[ybuf] (tf32) ----
    auto dw = [&](int cc, int xbuf, int ybuf) {
        const float* xs = (const float*)(smc + XB_OFF + xbuf * XB_SZ);
        uint32_t* Yw = (uint32_t*)(smc + YB_OFF + ybuf * YB_SZ);
        const float* wb = dws + g * 2304 + (cc * 8) * 9;
        float y[8];
        if (g < 2) {                // horizontal 1x9, center row r=4
            #pragma unroll
            for (int lc = 0; lc < 8; ++lc) {
                const float* xr = xs + lc * 1152 + 4 * 128;
                const float* w = wb + lc * 9;
                float s = 0.f;
                #pragma unroll
                for (int k = 0; k < 9; ++k) {
                    int nx = n + k - 4;
                    if ((unsigned)nx < 128u) s = fmaf(w[k], xr[nx], s);
                }
                y[lc] = s;
            }
        } else {                    // vertical 9x1
            #pragma unroll
            for (int lc = 0; lc < 8; ++lc) {
                const float* xc = xs + lc * 1152 + n;
                const float* w = wb + lc * 9;
                float s = 0.f;
                #pragma unroll
                for (int k = 0; k < 9; ++k) s = fmaf(w[k], xc[k * 128], s);
                y[lc] = s;
            }
        }
        #pragma unroll
        for (int lc = 0; lc < 8; ++lc)
            Yw[(g * 8 + lc) * 136 + n] = f2tf32(y[lc]);   // conflict-free: n consecutive
    };

    // ---- prologue ----
    px(0, 0); pa(0, 0);
    asm volatile("cp.async.commit_group;" ::: "memory");
    px(1, 1);
    asm volatile("cp.async.commit_group;" ::: "memory");
    asm volatile("cp.async.wait_group 0;" ::: "memory");
    __syncthreads();
    dw(0, 0, 0);
    __syncthreads();

    float acc[4][4][4];
    #pragma unroll
    for (int i = 0; i < 4; ++i)
        #pragma unroll
        for (int j = 0; j < 4; ++j)
            #pragma unroll
            for (int e = 0; e < 4; ++e) acc[i][j][e] = 0.f;

    const int fr = lane >> 2, fq = lane & 3;   // fragment row/col within 8x4

    // ---- main loop: one barrier per chunk; dw(c+1) and mma(c) share the window ----
    for (int c = 0; c < NCH; ++c) {
        const int buf = c & 1;
        if (c + 1 < NCH) pa(c + 1, buf ^ 1);
        if (c + 2 < NCH) px(c + 2, buf);
        asm volatile("cp.async.commit_group;" ::: "memory");

        if (c + 1 < NCH) dw(c + 1, buf ^ 1, buf ^ 1);

        {   // MMA chunk c: single-pass tf32, K=32 in 4 ksteps of 8
            const uint32_t* A = (const uint32_t*)(smc + AB_OFF + buf * AB_SZ);
            const uint32_t* Y = (const uint32_t*)(smc + YB_OFF + buf * YB_SZ);
            #pragma unroll
            for (int ks = 0; ks < 4; ++ks) {
                const int k0 = ks * 8;
                uint32_t a[4][4];
                #pragma unroll
                for (int mt = 0; mt < 4; ++mt) {
                    const uint32_t* Ar = A + (wm + mt * 16 + fr) * 36 + k0 + fq;
                    a[mt][0] = Ar[0];
                    a[mt][1] = Ar[8 * 36];
                    a[mt][2] = Ar[4];
                    a[mt][3] = Ar[8 * 36 + 4];
                }
                uint32_t bf[4][2];
                #pragma unroll
                for (int nt = 0; nt < 4; ++nt) {
                    const int col = wn + nt * 8 + fr;
                    bf[nt][0] = Y[(k0 + fq) * 136 + col];
                    bf[nt][1] = Y[(k0 + fq + 4) * 136 + col];
                }
                #pragma unroll
                for (int mt = 0; mt < 4; ++mt)
                    #pragma unroll
                    for (int nt = 0; nt < 4; ++nt)
                        mma_tf32(acc[mt][nt], a[mt], bf[nt]);
            }
        }

        asm volatile("cp.async.wait_group 0;" ::: "memory");
        __syncthreads();
    }

    // ---- epilogue: ReLU + store (D fragment layout) ----
    const int g2 = lane >> 2, cq = lane & 3;
    #pragma unroll
    for (int mt = 0; mt < 4; ++mt) {
        const int o0 = wm + mt * 16 + g2;
        #pragma unroll
        for (int nt = 0; nt < 4; ++nt) {
            const int n0 = wn + nt * 8 + cq * 2;
            float* p = out + (((long)(b * 256 + o0)) * HH + h) * WW + n0;
            float2 v0, v1;
            v0.x = fmaxf(acc[mt][nt][0], 0.f);
            v0.y = fmaxf(acc[mt][nt][1], 0.f);
            v1.x = fmaxf(acc[mt][nt][2], 0.f);
            v1.y = fmaxf(acc[mt][nt][3], 0.f);
            *(float2*)p = v0;
            *(float2*)(p + 8L * HH * WW) = v1;
        }
    }
}

// ================= launch =================
extern "C" void kernel_launch(void* const* d_in, const int* in_sizes, int n_in,
                              void* d_out, int out_size)
{
    const float* x     = (const float*)d_in[0];
    const float* wh1   = (const float*)d_in[1];
    const float* wh2   = (const float*)d_in[2];
    const float* wv1   = (const float*)d_in[3];
    const float* wv2   = (const float*)d_in[4];
    const float* wproj = (const float*)d_in[5];
    float* out = (float*)d_out;

    se_prep<<<1024, 256>>>(wproj);

    cudaFuncSetAttribute(se_main, cudaFuncAttributeMaxDynamicSharedMemorySize, SMEM_BYTES);
    dim3 grid(HH, BB);
    se_main<<<grid, 512, SMEM_BYTES>>>(x, wh1, wh2, wv1, wv2, out);
}

// round 5
// speedup vs baseline: 5.1078x; 1.1911x over previous
#include <cuda_runtime.h>
#include <cuda_bf16.h>
#include <cstdint>

#define HH 128
#define WW 128
#define BB 8
#define NCH 32            // 32 k-chunks; each = 8 input channels x 4 branches = 32 y-channels

// ---- smem byte layout ----
#define XB_OFF 0                      // 2 x 36864 : x fp32 [8ch][9rows][128]
#define XB_SZ  36864
#define AB_OFF 73728                  // 2 x 36864 : A tf32 [256 m][36 words] (stride 144B)
#define AB_SZ  36864
#define YB_OFF 147456                 // 2 x 17408 : y tf32 [32 k][136 words] (stride 544B)
#define YB_SZ  17408
#define DW_OFF 182272                 // 9216 floats (4 x 256 x 9)
#define SMEM_BYTES 219136

// wproj pre-converted to tf32: [chunk(32)][m(256)][k(32)] u32
__device__ uint32_t g_A_tf32[32 * 256 * 32];

// ================= helpers =================
__device__ __forceinline__ uint32_t smem_u32(const void* p) {
    uint32_t a;
    asm("{ .reg .u64 t; cvta.to.shared.u64 t, %1; cvt.u32.u64 %0, t; }" : "=r"(a) : "l"(p));
    return a;
}
__device__ __forceinline__ void cpa16(uint32_t dst, const void* src, int sz) {
    unsigned long long g = (unsigned long long)__cvta_generic_to_global((void*)src);
    asm volatile("cp.async.cg.shared.global [%0], [%1], 16, %2;" :: "r"(dst), "l"(g), "r"(sz));
}
__device__ __forceinline__ uint32_t f2tf32(float v) {
    uint32_t u;
    asm("cvt.rna.tf32.f32 %0, %1;" : "=r"(u) : "f"(v));
    return u;
}
__device__ __forceinline__ void ldsm4(uint32_t* r, uint32_t addr) {
    asm volatile("ldmatrix.sync.aligned.m8n8.x4.shared.b16 {%0,%1,%2,%3}, [%4];"
        : "=r"(r[0]), "=r"(r[1]), "=r"(r[2]), "=r"(r[3]) : "r"(addr));
}
__device__ __forceinline__ void mma_tf32(float* d, const uint32_t* a, const uint32_t* b) {
    asm volatile("mma.sync.aligned.m16n8k8.row.col.f32.tf32.tf32.f32 "
        "{%0,%1,%2,%3}, {%4,%5,%6,%7}, {%8,%9}, {%0,%1,%2,%3};"
        : "+f"(d[0]), "+f"(d[1]), "+f"(d[2]), "+f"(d[3])
        : "r"(a[0]), "r"(a[1]), "r"(a[2]), "r"(a[3]), "r"(b[0]), "r"(b[1]));
}

// ================= prep: wproj -> tf32, chunked layout =================
__global__ void se_prep(const float* __restrict__ wproj)
{
    int idx = blockIdx.x * 256 + threadIdx.x;   // 262144
    int k = idx & 31;
    int m = (idx >> 5) & 255;
    int c = idx >> 13;
    int br = k >> 3, lc = k & 7;
    float v = wproj[m * 1024 + br * 256 + c * 8 + lc];
    g_A_tf32[(c * 256 + m) * 32 + k] = f2tf32(v);
}

// ================= main =================
__global__ __launch_bounds__(512, 1)
void se_main(const float* __restrict__ x,
             const float* __restrict__ wh1, const float* __restrict__ wh2,
             const float* __restrict__ wv1, const float* __restrict__ wv2,
             float* __restrict__ out)
{
    extern __shared__ char smc[];
    float* smf = (float*)smc;
    const uint32_t sb = smem_u32(smc);
    const int h = blockIdx.x, b = blockIdx.y;
    const int t = threadIdx.x, lane = t & 31, wid = t >> 5;
    const int wm = (wid & 3) * 64;       // output-channel tile base (M)
    const int wn = (wid >> 2) * 32;      // pixel tile base (N)

    // depthwise mapping: pixel group ng (4 px), branch gg, channel pair c2
    const int ng = t & 31, gg = (t >> 5) & 3, c2 = t >> 7;
    const int n0 = ng * 4;

    // stage depthwise weights (fp32)
    float* dws = smf + DW_OFF / 4;
    for (int i = t; i < 9216; i += 512) {
        int sel = i / 2304, off = i - sel * 2304;
        const float* p = (sel == 0) ? wh1 : (sel == 1) ? wh2 : (sel == 2) ? wv1 : wv2;
        dws[i] = p[off];
    }

    const float* xb = x + (long)b * 256 * HH * WW;

    // ---- prefetch lambdas ----
    auto px = [&](int c, int dbuf) {
        for (int i = t; i < 2304; i += 512) {
            int ci = i / 288, rem = i - ci * 288;
            int r = rem >> 5, q = rem & 31;
            int hh = h + r - 4;
            int hcl = hh < 0 ? 0 : (hh > 127 ? 127 : hh);
            const float* src = xb + (((long)(c * 8 + ci)) * HH + hcl) * WW + q * 4;
            uint32_t dst = sb + XB_OFF + dbuf * XB_SZ + (uint32_t)((ci * 1152 + r * 128 + q * 4) * 4);
            cpa16(dst, src, ((unsigned)hh < 128u) ? 16 : 0);
        }
    };
    auto pa = [&](int c, int dbuf) {
        for (int i = t; i < 2048; i += 512) {
            int m = i >> 3, q = i & 7;
            const uint32_t* src = &g_A_tf32[(c * 256 + m) * 32 + q * 4];
            uint32_t dst = sb + AB_OFF + dbuf * AB_SZ + (uint32_t)(m * 144 + q * 16);
            cpa16(dst, src, 16);
        }
    };

    // ---- depthwise: chunk cc, 4 pixels x 2 channels per thread, vectorized ----
    auto dw = [&](int cc, int xbuf, int ybuf) {
        const float* xs = (const float*)(smc + XB_OFF + xbuf * XB_SZ);
        uint32_t* Yw = (uint32_t*)(smc + YB_OFF + ybuf * YB_SZ);
        #pragma unroll
        for (int e = 0; e < 2; ++e) {
            const int lc = c2 * 2 + e;               // channel 0..7 within chunk
            const int kk = gg * 8 + lc;              // y-channel (k index)
            const float* w = dws + gg * 2304 + (cc * 8 + lc) * 9;
            float o0, o1, o2, o3;
            if (gg < 2) {            // horizontal 1x9, center row
                const float* xr = xs + lc * 1152 + 4 * 128;
                float xv[12];
                float4 v = (ng > 0) ? *(const float4*)(xr + n0 - 4) : make_float4(0.f, 0.f, 0.f, 0.f);
                xv[0] = v.x; xv[1] = v.y; xv[2] = v.z; xv[3] = v.w;
                v = *(const float4*)(xr + n0);
                xv[4] = v.x; xv[5] = v.y; xv[6] = v.z; xv[7] = v.w;
                v = (ng < 31) ? *(const float4*)(xr + n0 + 4) : make_float4(0.f, 0.f, 0.f, 0.f);
                xv[8] = v.x; xv[9] = v.y; xv[10] = v.z; xv[11] = v.w;
                o0 = o1 = o2 = o3 = 0.f;
                #pragma unroll
                for (int k = 0; k < 9; ++k) {
                    const float wk = w[k];
                    o0 = fmaf(wk, xv[k],     o0);
                    o1 = fmaf(wk, xv[k + 1], o1);
                    o2 = fmaf(wk, xv[k + 2], o2);
                    o3 = fmaf(wk, xv[k + 3], o3);
                }
            } else {                 // vertical 9x1
                const float* xc = xs + lc * 1152 + n0;
                o0 = o1 = o2 = o3 = 0.f;
                #pragma unroll
                for (int r = 0; r < 9; ++r) {
                    const float4 v = *(const float4*)(xc + r * 128);
                    const float wk = w[r];
                    o0 = fmaf(wk, v.x, o0);
                    o1 = fmaf(wk, v.y, o1);
                    o2 = fmaf(wk, v.z, o2);
                    o3 = fmaf(wk, v.w, o3);
                }
            }
            uint4 st;
            st.x = f2tf32(o0); st.y = f2tf32(o1); st.z = f2tf32(o2); st.w = f2tf32(o3);
            *(uint4*)(Yw + kk * 136 + n0) = st;      // lanes consecutive -> conflict-free
        }
    };

    // ---- prologue ----
    px(0, 0); pa(0, 0);
    asm volatile("cp.async.commit_group;" ::: "memory");
    px(1, 1);
    asm volatile("cp.async.commit_group;" ::: "memory");
    asm volatile("cp.async.wait_group 0;" ::: "memory");
    __syncthreads();
    dw(0, 0, 0);
    __syncthreads();

    float acc[4][4][4];
    #pragma unroll
    for (int i = 0; i < 4; ++i)
        #pragma unroll
        for (int j = 0; j < 4; ++j)
            #pragma unroll
            for (int e = 0; e < 4; ++e) acc[i][j][e] = 0.f;

    const int fr = lane >> 2, fq = lane & 3;
    // per-lane ldmatrix A address offset: row=(lane&7)+((lane>>3)&1)*8, colgrp=(lane>>4)*4 words
    const uint32_t aLane = (uint32_t)(((lane & 7) + ((lane >> 3) & 1) * 8) * 144 + ((lane >> 4) << 4));

    // ---- main loop: one barrier per chunk; dw(c+1) and mma(c) share the window ----
    for (int c = 0; c < NCH; ++c) {
        const int buf = c & 1;
        if (c + 1 < NCH) pa(c + 1, buf ^ 1);
        if (c + 2 < NCH) px(c + 2, buf);
        asm volatile("cp.async.commit_group;" ::: "memory");

        if (c + 1 < NCH) dw(c + 1, buf ^ 1, buf ^ 1);

        {   // MMA chunk c: tf32, K=32 in 4 ksteps of 8; A via ldmatrix, B scalar
            const uint32_t abase = sb + AB_OFF + (uint32_t)(buf * AB_SZ) + (uint32_t)(wm * 144) + aLane;
            const uint32_t* Y = (const uint32_t*)(smc + YB_OFF + buf * YB_SZ);
            #pragma unroll
            for (int ks = 0; ks < 4; ++ks) {
                const int k0 = ks * 8;
                uint32_t a[4][4];
                #pragma unroll
                for (int mt = 0; mt < 4; ++mt)
                    ldsm4(a[mt], abase + (uint32_t)(mt * 16 * 144 + k0 * 4));
                uint32_t bf[4][2];
                #pragma unroll
                for (int nt = 0; nt < 4; ++nt) {
                    const int col = wn + nt * 8 + fr;
                    bf[nt][0] = Y[(k0 + fq) * 136 + col];
                    bf[nt][1] = Y[(k0 + fq + 4) * 136 + col];
                }
                #pragma unroll
                for (int mt = 0; mt < 4; ++mt)
                    #pragma unroll
                    for (int nt = 0; nt < 4; ++nt)
                        mma_tf32(acc[mt][nt], a[mt], bf[nt]);
            }
        }

        asm volatile("cp.async.wait_group 0;" ::: "memory");
        __syncthreads();
    }

    // ---- epilogue: ReLU + store (D fragment layout) ----
    const int g2 = lane >> 2, cq = lane & 3;
    #pragma unroll
    for (int mt = 0; mt < 4; ++mt) {
        const int o0 = wm + mt * 16 + g2;
        #pragma unroll
        for (int nt = 0; nt < 4; ++nt) {
            const int nn0 = wn + nt * 8 + cq * 2;
            float* p = out + (((long)(b * 256 + o0)) * HH + h) * WW + nn0;
            float2 v0, v1;
            v0.x = fmaxf(acc[mt][nt][0], 0.f);
            v0.y = fmaxf(acc[mt][nt][1], 0.f);
            v1.x = fmaxf(acc[mt][nt][2], 0.f);
            v1.y = fmaxf(acc[mt][nt][3], 0.f);
            *(float2*)p = v0;
            *(float2*)(p + 8L * HH * WW) = v1;
        }
    }
}

// ================= launch =================
extern "C" void kernel_launch(void* const* d_in, const int* in_sizes, int n_in,
                              void* d_out, int out_size)
{
    const float* x     = (const float*)d_in[0];
    const float* wh1   = (const float*)d_in[1];
    const float* wh2   = (const float*)d_in[2];
    const float* wv1   = (const float*)d_in[3];
    const float* wv2   = (const float*)d_in[4];
    const float* wproj = (const float*)d_in[5];
    float* out = (float*)d_out;

    se_prep<<<1024, 256>>>(wproj);

    cudaFuncSetAttribute(se_main, cudaFuncAttributeMaxDynamicSharedMemorySize, SMEM_BYTES);
    dim3 grid(HH, BB);
    se_main<<<grid, 512, SMEM_BYTES>>>(x, wh1, wh2, wv1, wv2, out);
}

// round 6
// speedup vs baseline: 5.3304x; 1.0436x over previous
#include <cuda_runtime.h>
#include <cstdint>

#define HH 128
#define WW 128
#define BB 8
#define NCH 32            // 32 k-chunks; each = 8 input channels x 4 branches = 32 y-channels

// ---- smem byte layout (per CTA) ----
#define AB_OFF 0                      // 2 x 36864 : A tf32 [256 m][36 words] (stride 144B)
#define AB_SZ  36864
#define YB_OFF 73728                  // 2 x 9216 : Y tf32 [32 k][72 words] (stride 288B)
#define YB_SZ  9216
#define SMEM_BYTES 92160

// wproj pre-converted to tf32: [chunk(32)][m(256)][k(32)] u32
__device__ uint32_t g_A_tf32[32 * 256 * 32];

// ================= helpers =================
__device__ __forceinline__ uint32_t smem_u32(const void* p) {
    uint32_t a;
    asm("{ .reg .u64 t; cvta.to.shared.u64 t, %1; cvt.u32.u64 %0, t; }" : "=r"(a) : "l"(p));
    return a;
}
__device__ __forceinline__ void cpa16(uint32_t dst, const void* src) {
    unsigned long long g = (unsigned long long)__cvta_generic_to_global((void*)src);
    asm volatile("cp.async.cg.shared.global [%0], [%1], 16;" :: "r"(dst), "l"(g));
}
__device__ __forceinline__ uint32_t f2tf32(float v) {
    uint32_t u;
    asm("cvt.rna.tf32.f32 %0, %1;" : "=r"(u) : "f"(v));
    return u;
}
__device__ __forceinline__ void ldsm4(uint32_t* r, uint32_t addr) {
    asm volatile("ldmatrix.sync.aligned.m8n8.x4.shared.b16 {%0,%1,%2,%3}, [%4];"
        : "=r"(r[0]), "=r"(r[1]), "=r"(r[2]), "=r"(r[3]) : "r"(addr));
}
__device__ __forceinline__ void mma_tf32(float* d, const uint32_t* a, const uint32_t* b) {
    asm volatile("mma.sync.aligned.m16n8k8.row.col.f32.tf32.tf32.f32 "
        "{%0,%1,%2,%3}, {%4,%5,%6,%7}, {%8,%9}, {%0,%1,%2,%3};"
        : "+f"(d[0]), "+f"(d[1]), "+f"(d[2]), "+f"(d[3])
        : "r"(a[0]), "r"(a[1]), "r"(a[2]), "r"(a[3]), "r"(b[0]), "r"(b[1]));
}

// ================= prep: wproj -> tf32, chunked layout =================
__global__ void se_prep(const float* __restrict__ wproj)
{
    int idx = blockIdx.x * 256 + threadIdx.x;   // 262144
    int k = idx & 31;
    int m = (idx >> 5) & 255;
    int c = idx >> 13;
    int br = k >> 3, lc = k & 7;
    float v = wproj[m * 1024 + br * 256 + c * 8 + lc];
    g_A_tf32[(c * 256 + m) * 32 + k] = f2tf32(v);
}

// ================= main =================
__global__ __launch_bounds__(256, 2)
void se_main(const float* __restrict__ x,
             const float* __restrict__ wh1, const float* __restrict__ wh2,
             const float* __restrict__ wv1, const float* __restrict__ wv2,
             float* __restrict__ out)
{
    extern __shared__ char smc[];
    const uint32_t sb = smem_u32(smc);
    const int half = blockIdx.x, h = blockIdx.y, b = blockIdx.z;
    const int t = threadIdx.x, lane = t & 31, wid = t >> 5;
    const int wm = (wid & 3) * 64;       // output-channel tile base (M)
    const int wn = (wid >> 2) * 32;      // pixel tile base within 64-px half (N)

    // depthwise mapping: 16 pixel-groups x 8 channels x 2 conv-groups (H / V)
    const int ng = t & 15, lc = (t >> 4) & 7, grp = t >> 7;
    const int p0 = half * 64 + ng * 4;   // global pixel base (4 px per thread)
    const int n0 = ng * 4;               // local pixel base

    const float* xb = x + (long)b * 256 * HH * WW;

    // ---- A prefetch: chunk c -> smem buffer dbuf ----
    auto pa = [&](int c, int dbuf) {
        #pragma unroll
        for (int i = 0; i < 8; ++i) {
            int idx = t + i * 256;           // 0..2047
            int m = idx >> 3, q = idx & 7;
            cpa16(sb + AB_OFF + (uint32_t)(dbuf * AB_SZ + m * 144 + q * 16),
                  &g_A_tf32[(c * 256 + m) * 32 + q * 4]);
        }
    };

    // ---- depthwise: chunk cc -> Y[ybuf], x straight from gmem ----
    auto dw = [&](int cc, int ybuf) {
        uint32_t* Yw = (uint32_t*)(smc + YB_OFF + ybuf * YB_SZ);
        const int gch = cc * 8 + lc;
        const float* xch = xb + (long)gch * HH * WW;
        float ya0 = 0.f, ya1 = 0.f, ya2 = 0.f, ya3 = 0.f;
        float yb0 = 0.f, yb1 = 0.f, yb2 = 0.f, yb3 = 0.f;
        int kkA, kkB;
        if (grp == 0) {           // horizontal 1x9 on row h (both wh1, wh2)
            const float* xr = xch + h * WW;
            float xv[12];
            if (p0 >= 4) {
                float4 v = *(const float4*)(xr + p0 - 4);
                xv[0] = v.x; xv[1] = v.y; xv[2] = v.z; xv[3] = v.w;
            } else { xv[0] = xv[1] = xv[2] = xv[3] = 0.f; }
            {
                float4 v = *(const float4*)(xr + p0);
                xv[4] = v.x; xv[5] = v.y; xv[6] = v.z; xv[7] = v.w;
            }
            if (p0 + 7 < 128) {
                float4 v = *(const float4*)(xr + p0 + 4);
                xv[8] = v.x; xv[9] = v.y; xv[10] = v.z; xv[11] = v.w;
            } else { xv[8] = xv[9] = xv[10] = xv[11] = 0.f; }
            const float* w1 = wh1 + gch * 9;
            const float* w2 = wh2 + gch * 9;
            #pragma unroll
            for (int k = 0; k < 9; ++k) {
                const float a = w1[k], c2 = w2[k];
                ya0 = fmaf(a, xv[k],     ya0); yb0 = fmaf(c2, xv[k],     yb0);
                ya1 = fmaf(a, xv[k + 1], ya1); yb1 = fmaf(c2, xv[k + 1], yb1);
                ya2 = fmaf(a, xv[k + 2], ya2); yb2 = fmaf(c2, xv[k + 2], yb2);
                ya3 = fmaf(a, xv[k + 3], ya3); yb3 = fmaf(c2, xv[k + 3], yb3);
            }
            kkA = lc; kkB = 8 + lc;
        } else {                  // vertical 9x1 (both wv1, wv2)
            const float* w1 = wv1 + gch * 9;
            const float* w2 = wv2 + gch * 9;
            #pragma unroll
            for (int r = 0; r < 9; ++r) {
                const int hh2 = h + r - 4;
                if ((unsigned)hh2 < 128u) {
                    const float4 v = *(const float4*)(xch + hh2 * WW + p0);
                    const float a = w1[r], c2 = w2[r];
                    ya0 = fmaf(a, v.x, ya0); yb0 = fmaf(c2, v.x, yb0);
                    ya1 = fmaf(a, v.y, ya1); yb1 = fmaf(c2, v.y, yb1);
                    ya2 = fmaf(a, v.z, ya2); yb2 = fmaf(c2, v.z, yb2);
                    ya3 = fmaf(a, v.w, ya3); yb3 = fmaf(c2, v.w, yb3);
                }
            }
            kkA = 16 + lc; kkB = 24 + lc;
        }
        uint4 s0, s1;
        s0.x = f2tf32(ya0); s0.y = f2tf32(ya1); s0.z = f2tf32(ya2); s0.w = f2tf32(ya3);
        s1.x = f2tf32(yb0); s1.y = f2tf32(yb1); s1.z = f2tf32(yb2); s1.w = f2tf32(yb3);
        *(uint4*)(Yw + kkA * 72 + n0) = s0;
        *(uint4*)(Yw + kkB * 72 + n0) = s1;
    };

    // ---- prologue ----
    pa(0, 0);
    asm volatile("cp.async.commit_group;" ::: "memory");
    dw(0, 0);
    asm volatile("cp.async.wait_group 0;" ::: "memory");
    __syncthreads();

    float acc[4][4][4];
    #pragma unroll
    for (int i = 0; i < 4; ++i)
        #pragma unroll
        for (int j = 0; j < 4; ++j)
            #pragma unroll
            for (int e = 0; e < 4; ++e) acc[i][j][e] = 0.f;

    const int fr = lane >> 2, fq = lane & 3;
    const uint32_t aLane = (uint32_t)(((lane & 7) + ((lane >> 3) & 1) * 8) * 144 + ((lane >> 4) << 4));

    // ---- main loop: one barrier per chunk ----
    for (int c = 0; c < NCH; ++c) {
        const int buf = c & 1;
        if (c + 1 < NCH) {
            pa(c + 1, buf ^ 1);
            asm volatile("cp.async.commit_group;" ::: "memory");
            dw(c + 1, buf ^ 1);
        }

        {   // MMA chunk c: tf32, K=32 in 4 ksteps of 8; A via ldmatrix, B scalar
            const uint32_t abase = sb + AB_OFF + (uint32_t)(buf * AB_SZ) + (uint32_t)(wm * 144) + aLane;
            const uint32_t* Y = (const uint32_t*)(smc + YB_OFF + buf * YB_SZ);
            #pragma unroll
            for (int ks = 0; ks < 4; ++ks) {
                const int k0 = ks * 8;
                uint32_t a[4][4];
                #pragma unroll
                for (int mt = 0; mt < 4; ++mt)
                    ldsm4(a[mt], abase + (uint32_t)(mt * 16 * 144 + k0 * 4));
                uint32_t bf[4][2];
                #pragma unroll
                for (int nt = 0; nt < 4; ++nt) {
                    const int col = wn + nt * 8 + fr;
                    bf[nt][0] = Y[(k0 + fq) * 72 + col];
                    bf[nt][1] = Y[(k0 + fq + 4) * 72 + col];
                }
                #pragma unroll
                for (int mt = 0; mt < 4; ++mt)
                    #pragma unroll
                    for (int nt = 0; nt < 4; ++nt)
                        mma_tf32(acc[mt][nt], a[mt], bf[nt]);
            }
        }

        asm volatile("cp.async.wait_group 0;" ::: "memory");
        __syncthreads();
    }

    // ---- epilogue: ReLU + store (D fragment layout) ----
    const int g2 = lane >> 2, cq = lane & 3;
    #pragma unroll
    for (int mt = 0; mt < 4; ++mt) {
        const int o0 = wm + mt * 16 + g2;
        #pragma unroll
        for (int nt = 0; nt < 4; ++nt) {
            const int nn0 = half * 64 + wn + nt * 8 + cq * 2;
            float* p = out + (((long)(b * 256 + o0)) * HH + h) * WW + nn0;
            float2 v0, v1;
            v0.x = fmaxf(acc[mt][nt][0], 0.f);
            v0.y = fmaxf(acc[mt][nt][1], 0.f);
            v1.x = fmaxf(acc[mt][nt][2], 0.f);
            v1.y = fmaxf(acc[mt][nt][3], 0.f);
            *(float2*)p = v0;
            *(float2*)(p + 8L * HH * WW) = v1;
        }
    }
}

// ================= launch =================
extern "C" void kernel_launch(void* const* d_in, const int* in_sizes, int n_in,
                              void* d_out, int out_size)
{
    const float* x     = (const float*)d_in[0];
    const float* wh1   = (const float*)d_in[1];
    const float* wh2   = (const float*)d_in[2];
    const float* wv1   = (const float*)d_in[3];
    const float* wv2   = (const float*)d_in[4];
    const float* wproj = (const float*)d_in[5];
    float* out = (float*)d_out;

    se_prep<<<1024, 256>>>(wproj);

    cudaFuncSetAttribute(se_main, cudaFuncAttributeMaxDynamicSharedMemorySize, SMEM_BYTES);
    dim3 grid(2, HH, BB);
    se_main<<<grid, 256, SMEM_BYTES>>>(x, wh1, wh2, wv1, wv2, out);
}